// round 1
// baseline (speedup 1.0000x reference)
#include <cuda_runtime.h>

// Problem constants
#define BB   32
#define CIN  64
#define OCH  128
#define HH   64
#define WW   64
#define PP   (HH*WW)          // 4096 pixels
#define OH   32
#define OW   32
#define SLICE ((size_t)BB*OCH*OH*OW)   // 4,194,304 elements per output slice

// Scratch (device globals: no allocation allowed in kernel_launch)
__device__ float g_l1  [BB*OCH*HH*WW];
__device__ float g_l2  [BB*OCH*HH*WW];
__device__ float g_l3  [BB*OCH*HH*WW];
__device__ float g_prev[BB*OCH*HH*WW];
__device__ float g_aux [BB*OCH*OH*OW];
__device__ float g_attn[BB*PP];

__device__ __forceinline__ float lrelu(float x) { return x >= 0.f ? x : 0.1f * x; }

// ---------------------------------------------------------------------------
// Attention: logits[b,p] = <lin_w[p,:], out1[b,:,p]> + lin_b[p]; softmax over p.
// One block per batch item, 256 threads, 16 pixels per thread.
// ---------------------------------------------------------------------------
__global__ void attn_kernel(const float* __restrict__ out1,
                            const float* __restrict__ lin_w,
                            const float* __restrict__ lin_b,
                            float* __restrict__ attn)
{
    const int b   = blockIdx.x;
    const int tid = threadIdx.x;
    const float* xb = out1 + (size_t)b * CIN * PP;

    float logit[16];
    float lmax = -1e30f;
#pragma unroll
    for (int i = 0; i < 16; i++) {
        const int p = tid + i * 256;
        float acc = lin_b[p];
        const float4* wr = (const float4*)(lin_w + (size_t)p * CIN);
#pragma unroll
        for (int c4 = 0; c4 < CIN / 4; c4++) {
            float4 w4 = wr[c4];
            acc = fmaf(w4.x, xb[(c4*4+0)*PP + p], acc);
            acc = fmaf(w4.y, xb[(c4*4+1)*PP + p], acc);
            acc = fmaf(w4.z, xb[(c4*4+2)*PP + p], acc);
            acc = fmaf(w4.w, xb[(c4*4+3)*PP + p], acc);
        }
        logit[i] = acc;
        lmax = fmaxf(lmax, acc);
    }

    __shared__ float red[256];
    red[tid] = lmax; __syncthreads();
    for (int s = 128; s > 0; s >>= 1) {
        if (tid < s) red[tid] = fmaxf(red[tid], red[tid + s]);
        __syncthreads();
    }
    const float m = red[0]; __syncthreads();

    float lsum = 0.f;
#pragma unroll
    for (int i = 0; i < 16; i++) { logit[i] = expf(logit[i] - m); lsum += logit[i]; }
    red[tid] = lsum; __syncthreads();
    for (int s = 128; s > 0; s >>= 1) {
        if (tid < s) red[tid] += red[tid + s];
        __syncthreads();
    }
    const float inv = 1.0f / red[0];
#pragma unroll
    for (int i = 0; i < 16; i++)
        attn[(size_t)b * PP + tid + i * 256] = logit[i] * inv;
}

// ---------------------------------------------------------------------------
// Stride-1 3x3 conv + bias + lrelu. Input may be a channel-concat of two
// tensors (in0 has csplit channels, in1 the rest).
// Block: 32x32 output tile, 8 out-channels; 256 threads; each thread does
// 1 row x 4 cols x 8 ocs (32 accumulators). Smem row stride 35 -> the
// (4 rows x 8 lanes) warp footprint covers all 32 banks (conflict-free).
// ---------------------------------------------------------------------------
template<int CI>
__global__ __launch_bounds__(256)
void conv_s1(const float* __restrict__ in0, const float* __restrict__ in1, int csplit,
             const float* __restrict__ wgt, const float* __restrict__ bias,
             float* __restrict__ out)
{
    __shared__ float s_in[8][34][35];
    __shared__ float s_w[8][8][9];

    const int tid = threadIdx.x;
    const int tx  = tid & 7;        // 0..7  (x / 4)
    const int ty  = tid >> 3;       // 0..31 (row in tile)
    const int tx0 = (blockIdx.x & 1) * 32;
    const int ty0 = (blockIdx.x >> 1) * 32;
    const int ocg = blockIdx.y;     // 0..15
    const int b   = blockIdx.z;
    const int x4  = tx * 4;

    float acc[8][4];
#pragma unroll
    for (int o = 0; o < 8; o++)
#pragma unroll
        for (int j = 0; j < 4; j++) acc[o][j] = 0.f;

    for (int ci0 = 0; ci0 < CI; ci0 += 8) {
        // weights for 8 ci x 8 oc
        for (int idx = tid; idx < 8*8*9; idx += 256) {
            int ci = idx / 72; int r = idx - ci*72; int oc = r / 9; int k = r - oc*9;
            s_w[ci][oc][k] = wgt[((size_t)(ocg*8 + oc) * CI + ci0 + ci) * 9 + k];
        }
        // 34x34 haloed input tile for 8 ci
        for (int idx = tid; idx < 8*34*34; idx += 256) {
            int ci = idx / (34*34); int r = idx - ci*(34*34);
            int iy = r / 34; int ix = r - iy*34;
            int gy = ty0 - 1 + iy, gx = tx0 - 1 + ix;
            float v = 0.f;
            if ((unsigned)gy < HH && (unsigned)gx < WW) {
                int cg = ci0 + ci;
                const float* src = (cg < csplit)
                    ? in0 + ((size_t)b * csplit + cg) * PP
                    : in1 + ((size_t)b * (CI - csplit) + (cg - csplit)) * PP;
                v = src[gy * WW + gx];
            }
            s_in[ci][iy][ix] = v;
        }
        __syncthreads();

#pragma unroll
        for (int ci = 0; ci < 8; ci++) {
            float r0[6], r1[6], r2[6];
#pragma unroll
            for (int cc = 0; cc < 6; cc++) {
                r0[cc] = s_in[ci][ty + 0][x4 + cc];
                r1[cc] = s_in[ci][ty + 1][x4 + cc];
                r2[cc] = s_in[ci][ty + 2][x4 + cc];
            }
#pragma unroll
            for (int oc = 0; oc < 8; oc++) {
                const float w0 = s_w[ci][oc][0], w1 = s_w[ci][oc][1], w2 = s_w[ci][oc][2];
                const float w3 = s_w[ci][oc][3], w4 = s_w[ci][oc][4], w5 = s_w[ci][oc][5];
                const float w6 = s_w[ci][oc][6], w7 = s_w[ci][oc][7], w8 = s_w[ci][oc][8];
#pragma unroll
                for (int j = 0; j < 4; j++) {
                    float a = acc[oc][j];
                    a = fmaf(r0[j+0], w0, a); a = fmaf(r0[j+1], w1, a); a = fmaf(r0[j+2], w2, a);
                    a = fmaf(r1[j+0], w3, a); a = fmaf(r1[j+1], w4, a); a = fmaf(r1[j+2], w5, a);
                    a = fmaf(r2[j+0], w6, a); a = fmaf(r2[j+1], w7, a); a = fmaf(r2[j+2], w8, a);
                    acc[oc][j] = a;
                }
            }
        }
        __syncthreads();
    }

#pragma unroll
    for (int oc = 0; oc < 8; oc++) {
        const float bv = bias[ocg*8 + oc];
        float4 v;
        v.x = lrelu(acc[oc][0] + bv);
        v.y = lrelu(acc[oc][1] + bv);
        v.z = lrelu(acc[oc][2] + bv);
        v.w = lrelu(acc[oc][3] + bv);
        size_t o = (((size_t)b * OCH + ocg*8 + oc) * HH + ty0 + ty) * WW + tx0 + x4;
        *(float4*)(out + o) = v;
    }
}

// ---------------------------------------------------------------------------
// Stride-2 3x3 conv + bias + lrelu (pad 1). Output 32x32.
// Block: out tile 16 rows x full 32 cols, 8 ocs; each thread 2 px (tx, tx+16).
// ---------------------------------------------------------------------------
template<int CI>
__global__ __launch_bounds__(256)
void conv_s2(const float* __restrict__ in0, const float* __restrict__ in1, int csplit,
             const float* __restrict__ wgt, const float* __restrict__ bias,
             float* __restrict__ out)
{
    __shared__ float s_in[4][33][67];
    __shared__ float s_w[4][8][9];

    const int tid = threadIdx.x;
    const int tx  = tid & 15;       // out col (and +16)
    const int ty  = tid >> 4;       // 0..15 out row in tile
    const int oy0 = blockIdx.x * 16;
    const int ocg = blockIdx.y;
    const int b   = blockIdx.z;

    float acc0[8], acc1[8];
#pragma unroll
    for (int o = 0; o < 8; o++) { acc0[o] = 0.f; acc1[o] = 0.f; }

    for (int ci0 = 0; ci0 < CI; ci0 += 4) {
        for (int idx = tid; idx < 4*8*9; idx += 256) {
            int ci = idx / 72; int r = idx - ci*72; int oc = r / 9; int k = r - oc*9;
            s_w[ci][oc][k] = wgt[((size_t)(ocg*8 + oc) * CI + ci0 + ci) * 9 + k];
        }
        for (int idx = tid; idx < 4*33*66; idx += 256) {
            int ci = idx / (33*66); int r = idx - ci*(33*66);
            int iy = r / 66; int ix = r - iy*66;
            int gy = 2*oy0 - 1 + iy, gx = ix - 1;
            float v = 0.f;
            if ((unsigned)gy < HH && (unsigned)gx < WW) {
                int cg = ci0 + ci;
                const float* src = (cg < csplit)
                    ? in0 + ((size_t)b * csplit + cg) * PP
                    : in1 + ((size_t)b * (CI - csplit) + (cg - csplit)) * PP;
                v = src[gy * WW + gx];
            }
            s_in[ci][iy][ix] = v;
        }
        __syncthreads();

#pragma unroll
        for (int ci = 0; ci < 4; ci++) {
#pragma unroll
            for (int ky = 0; ky < 3; ky++) {
#pragma unroll
                for (int kx = 0; kx < 3; kx++) {
                    const float v0 = s_in[ci][2*ty + ky][2*tx + kx];
                    const float v1 = s_in[ci][2*ty + ky][2*tx + 32 + kx];
#pragma unroll
                    for (int oc = 0; oc < 8; oc++) {
                        const float w = s_w[ci][oc][ky*3 + kx];
                        acc0[oc] = fmaf(v0, w, acc0[oc]);
                        acc1[oc] = fmaf(v1, w, acc1[oc]);
                    }
                }
            }
        }
        __syncthreads();
    }

#pragma unroll
    for (int oc = 0; oc < 8; oc++) {
        const float bv = bias[ocg*8 + oc];
        size_t base = (((size_t)b * OCH + ocg*8 + oc) * OH + oy0 + ty) * OW;
        out[base + tx]      = lrelu(acc0[oc] + bv);
        out[base + tx + 16] = lrelu(acc1[oc] + bv);
    }
}

// ---------------------------------------------------------------------------
// RoIAlign(full image, 32x32 bins, sampling_ratio=2) of prev*attn -> slice 2.
// ---------------------------------------------------------------------------
__global__ void bo3_kernel(const float* __restrict__ prev,
                           const float* __restrict__ attn,
                           float* __restrict__ out /* slice-2 base */)
{
    const int idx = blockIdx.x * 256 + threadIdx.x;
    const int ox = idx & 31, oy = (idx >> 5) & 31, bc = idx >> 10;
    const int b = bc >> 7;
    const float* pv = prev + (size_t)bc * PP;
    const float* at = attn + (size_t)b * PP;
    const float BIN = 63.0f / 32.0f;

    float acc = 0.f;
#pragma unroll
    for (int sy = 0; sy < 2; sy++) {
        const float ys = ((float)oy + 0.25f + 0.5f * sy) * BIN;
        const int y0 = (int)ys;
        const int y1 = min(y0 + 1, HH - 1);
        const float ly = ys - (float)y0, hy = 1.f - ly;
#pragma unroll
        for (int sx = 0; sx < 2; sx++) {
            const float xs = ((float)ox + 0.25f + 0.5f * sx) * BIN;
            const int x0 = (int)xs;
            const int x1 = min(x0 + 1, WW - 1);
            const float lx = xs - (float)x0, hx = 1.f - lx;
            const float f00 = pv[y0*WW + x0] * at[y0*WW + x0];
            const float f01 = pv[y0*WW + x1] * at[y0*WW + x1];
            const float f10 = pv[y1*WW + x0] * at[y1*WW + x0];
            const float f11 = pv[y1*WW + x1] * at[y1*WW + x1];
            acc += hy * (hx * f00 + lx * f01) + ly * (hx * f10 + lx * f11);
        }
    }
    out[idx] = acc * 0.25f;
}

// ---------------------------------------------------------------------------
// slice0 = RoIAlign(l2) + aux + slice1 + slice2
// ---------------------------------------------------------------------------
__global__ void combine_kernel(const float* __restrict__ l2,
                               const float* __restrict__ aux,
                               float* __restrict__ out /* full d_out */)
{
    const int idx = blockIdx.x * 256 + threadIdx.x;
    const int ox = idx & 31, oy = (idx >> 5) & 31, bc = idx >> 10;
    const float* src = l2 + (size_t)bc * PP;
    const float BIN = 63.0f / 32.0f;

    float acc = 0.f;
#pragma unroll
    for (int sy = 0; sy < 2; sy++) {
        const float ys = ((float)oy + 0.25f + 0.5f * sy) * BIN;
        const int y0 = (int)ys;
        const int y1 = min(y0 + 1, HH - 1);
        const float ly = ys - (float)y0, hy = 1.f - ly;
#pragma unroll
        for (int sx = 0; sx < 2; sx++) {
            const float xs = ((float)ox + 0.25f + 0.5f * sx) * BIN;
            const int x0 = (int)xs;
            const int x1 = min(x0 + 1, WW - 1);
            const float lx = xs - (float)x0, hx = 1.f - lx;
            acc += hy * (hx * src[y0*WW + x0] + lx * src[y0*WW + x1])
                 + ly * (hx * src[y1*WW + x0] + lx * src[y1*WW + x1]);
        }
    }
    out[idx] = acc * 0.25f + aux[idx] + out[SLICE + idx] + out[2*SLICE + idx];
}

// ---------------------------------------------------------------------------
extern "C" void kernel_launch(void* const* d_in, const int* in_sizes, int n_in,
                              void* d_out, int out_size)
{
    const float* out1   = (const float*)d_in[0];
    const float* out2   = (const float*)d_in[1];
    const float* out3   = (const float*)d_in[2];
    const float* w1     = (const float*)d_in[3];
    const float* b1     = (const float*)d_in[4];
    const float* w2     = (const float*)d_in[5];
    const float* b2     = (const float*)d_in[6];
    const float* w3     = (const float*)d_in[7];
    const float* b3     = (const float*)d_in[8];
    const float* w_aux  = (const float*)d_in[9];
    const float* b_aux  = (const float*)d_in[10];
    const float* w_b2   = (const float*)d_in[11];
    const float* b_b2   = (const float*)d_in[12];
    const float* w_prev = (const float*)d_in[13];
    const float* b_prev = (const float*)d_in[14];
    const float* lin_w  = (const float*)d_in[15];
    const float* lin_b  = (const float*)d_in[16];
    float* out = (float*)d_out;

    float *l1, *l2, *l3, *prev, *aux, *attn;
    cudaGetSymbolAddress((void**)&l1,   g_l1);
    cudaGetSymbolAddress((void**)&l2,   g_l2);
    cudaGetSymbolAddress((void**)&l3,   g_l3);
    cudaGetSymbolAddress((void**)&prev, g_prev);
    cudaGetSymbolAddress((void**)&aux,  g_aux);
    cudaGetSymbolAddress((void**)&attn, g_attn);

    const dim3 gs1(4, OCH/8, BB);   // stride-1 convs
    const dim3 gs2(2, OCH/8, BB);   // stride-2 convs
    const int  nPix = (int)(SLICE / 256);

    attn_kernel<<<BB, 256>>>(out1, lin_w, lin_b, attn);

    conv_s1<64 ><<<gs1, 256>>>(out1, nullptr, 64,  w1,     b1,     l1);
    conv_s1<128><<<gs1, 256>>>(l1,   nullptr, 128, w2,     b2,     l2);
    conv_s1<128><<<gs1, 256>>>(l2,   nullptr, 128, w3,     b3,     l3);
    conv_s1<128><<<gs1, 256>>>(out2, out3,    64,  w_prev, b_prev, prev);

    conv_s2<256><<<gs2, 256>>>(l1, l2,      128, w_b2,  b_b2,  out + SLICE);   // block_out2
    conv_s2<128><<<gs2, 256>>>(l3, nullptr, 128, w_aux, b_aux, aux);

    bo3_kernel<<<nPix, 256>>>(prev, attn, out + 2*SLICE);                      // block_out3
    combine_kernel<<<nPix, 256>>>(l2, aux, out);                               // block_out1 sum
}

// round 3
// speedup vs baseline: 1.5808x; 1.5808x over previous
#include <cuda_runtime.h>

// Problem constants
#define BB   32
#define CIN  64
#define OCH  128
#define HH   64
#define WW   64
#define PP   (HH*WW)          // 4096 pixels
#define OH   32
#define OW   32
#define SLICE ((size_t)BB*OCH*OH*OW)   // elements per output slice

// Scratch (device globals: no allocation allowed in kernel_launch)
__device__ float g_l1  [BB*OCH*HH*WW];
__device__ float g_l2  [BB*OCH*HH*WW];
__device__ float g_l3  [BB*OCH*HH*WW];
__device__ float g_prev[BB*OCH*HH*WW];
__device__ float g_aux [BB*OCH*OH*OW];
__device__ float g_attn[BB*PP];

__device__ __forceinline__ float lrelu(float x) { return x >= 0.f ? x : 0.1f * x; }

// ---------------------------------------------------------------------------
// Attention: logits[b,p] = <lin_w[p,:], out1[b,:,p]> + lin_b[p]; softmax over p.
// ---------------------------------------------------------------------------
__global__ void attn_kernel(const float* __restrict__ out1,
                            const float* __restrict__ lin_w,
                            const float* __restrict__ lin_b,
                            float* __restrict__ attn)
{
    const int b   = blockIdx.x;
    const int tid = threadIdx.x;
    const float* xb = out1 + (size_t)b * CIN * PP;

    float logit[16];
    float lmax = -1e30f;
#pragma unroll
    for (int i = 0; i < 16; i++) {
        const int p = tid + i * 256;
        float acc = lin_b[p];
        const float4* wr = (const float4*)(lin_w + (size_t)p * CIN);
#pragma unroll
        for (int c4 = 0; c4 < CIN / 4; c4++) {
            float4 w4 = wr[c4];
            acc = fmaf(w4.x, xb[(c4*4+0)*PP + p], acc);
            acc = fmaf(w4.y, xb[(c4*4+1)*PP + p], acc);
            acc = fmaf(w4.z, xb[(c4*4+2)*PP + p], acc);
            acc = fmaf(w4.w, xb[(c4*4+3)*PP + p], acc);
        }
        logit[i] = acc;
        lmax = fmaxf(lmax, acc);
    }

    __shared__ float red[256];
    red[tid] = lmax; __syncthreads();
    for (int s = 128; s > 0; s >>= 1) {
        if (tid < s) red[tid] = fmaxf(red[tid], red[tid + s]);
        __syncthreads();
    }
    const float m = red[0]; __syncthreads();

    float lsum = 0.f;
#pragma unroll
    for (int i = 0; i < 16; i++) { logit[i] = expf(logit[i] - m); lsum += logit[i]; }
    red[tid] = lsum; __syncthreads();
    for (int s = 128; s > 0; s >>= 1) {
        if (tid < s) red[tid] += red[tid + s];
        __syncthreads();
    }
    const float inv = 1.0f / red[0];
#pragma unroll
    for (int i = 0; i < 16; i++)
        attn[(size_t)b * PP + tid + i * 256] = logit[i] * inv;
}

// ---------------------------------------------------------------------------
// Stride-1 3x3 conv + bias + lrelu. Input may be channel-concat (in0|in1).
// Block: tile 32 rows x 64 cols, 8 out-channels, 256 threads.
// Thread: 1 row x 8 cols x 8 oc (64 acc). ci-chunk = 4.
// Smem padded so all operand loads are LDS.128:
//   input row stride 68 floats (16B-aligned rows), weights 9 -> 12 (k*4+i).
// ---------------------------------------------------------------------------
template<int CI>
__global__ __launch_bounds__(256, 2)
void conv_s1(const float* __restrict__ in0, const float* __restrict__ in1, int csplit,
             const float* __restrict__ wgt, const float* __restrict__ bias,
             float* __restrict__ out)
{
    __shared__ float s_in[4][34][68];   // 34 halo rows x 66 used cols
    __shared__ float s_w[4][8][12];     // [ci][oc][k*4 + i], i<3 used

    const int tid  = threadIdx.x;
    const int tx   = tid & 7;           // col group
    const int ty   = tid >> 3;          // 0..31 row in tile
    const int x8   = tx * 8;
    const int ty0  = blockIdx.x * 32;
    const int ocg  = blockIdx.y;        // 0..15
    const int b    = blockIdx.z;
    const int warp = tid >> 5;
    const int lane = tid & 31;

    float acc[8][8];
#pragma unroll
    for (int o = 0; o < 8; o++)
#pragma unroll
        for (int j = 0; j < 8; j++) acc[o][j] = 0.f;

    for (int ci0 = 0; ci0 < CI; ci0 += 4) {
        // ---- weights: 4 ci x 8 oc x 9, padded to k*4+i ----
#pragma unroll
        for (int idx = tid; idx < 4*8*9; idx += 256) {
            int ci = idx / 72; int r = idx - ci*72; int oc = r / 9; int kk = r - oc*9;
            s_w[ci][oc][(kk/3)*4 + (kk - (kk/3)*3)] =
                wgt[((size_t)(ocg*8 + oc) * CI + ci0 + ci) * 9 + kk];
        }
        // ---- input tile: 4 ci x 34 rows x 66 cols, no div/mod ----
#pragma unroll
        for (int ci = 0; ci < 4; ci++) {
            const int cg = ci0 + ci;
            const float* src = (cg < csplit)
                ? in0 + ((size_t)b * csplit + cg) * PP
                : in1 + ((size_t)b * (CI - csplit) + (cg - csplit)) * PP;
#pragma unroll
            for (int k = 0; k < 5; k++) {
                const int iy = warp + 8*k;
                if (k < 4 || iy < 34) {
                    const int gy = ty0 - 1 + iy;
                    const bool rowok = (unsigned)gy < HH;
                    const float* rowp = src + gy * WW;
                    float* srow = &s_in[ci][iy][0];
                    const int gx0 = lane - 1;
                    srow[lane]      = (rowok && (unsigned)gx0 < WW) ? rowp[gx0] : 0.f;
                    const int gx1 = lane + 31;
                    srow[lane + 32] = (rowok && gx1 < WW) ? rowp[gx1] : 0.f;
                    if (lane < 2) {
                        const int gx2 = lane + 63;
                        srow[lane + 64] = (rowok && gx2 < WW) ? rowp[gx2] : 0.f;
                    }
                }
            }
        }
        __syncthreads();

        // ---- compute: all LDS are .128 ----
#pragma unroll
        for (int ci = 0; ci < 4; ci++) {
#pragma unroll
            for (int k = 0; k < 3; k++) {
                const float4* rp = (const float4*)&s_in[ci][ty + k][x8];
                const float4 ra = rp[0], rb = rp[1], rc = rp[2];
                const float r[12] = {ra.x, ra.y, ra.z, ra.w,
                                     rb.x, rb.y, rb.z, rb.w,
                                     rc.x, rc.y, rc.z, rc.w};
#pragma unroll
                for (int oc = 0; oc < 8; oc++) {
                    const float4 w = *(const float4*)&s_w[ci][oc][k*4];
#pragma unroll
                    for (int j = 0; j < 8; j++) {
                        float a = acc[oc][j];
                        a = fmaf(r[j+0], w.x, a);
                        a = fmaf(r[j+1], w.y, a);
                        a = fmaf(r[j+2], w.z, a);
                        acc[oc][j] = a;
                    }
                }
            }
        }
        __syncthreads();
    }

#pragma unroll
    for (int oc = 0; oc < 8; oc++) {
        const float bv = bias[ocg*8 + oc];
        float4 v0, v1;
        v0.x = lrelu(acc[oc][0] + bv); v0.y = lrelu(acc[oc][1] + bv);
        v0.z = lrelu(acc[oc][2] + bv); v0.w = lrelu(acc[oc][3] + bv);
        v1.x = lrelu(acc[oc][4] + bv); v1.y = lrelu(acc[oc][5] + bv);
        v1.z = lrelu(acc[oc][6] + bv); v1.w = lrelu(acc[oc][7] + bv);
        size_t o = (((size_t)b * OCH + ocg*8 + oc) * HH + ty0 + ty) * WW + x8;
        *(float4*)(out + o)     = v0;
        *(float4*)(out + o + 4) = v1;
    }
}

// ---------------------------------------------------------------------------
// Stride-2 3x3 conv + bias + lrelu (pad 1). Output 32x32 (full image / block).
// Block: 16 out-channels, 256 threads; thread: 1 row x 4 cols x 16 oc.
// ci-chunk = 2. All operand loads LDS.128 (row stride 68, weights padded).
// ---------------------------------------------------------------------------
template<int CI>
__global__ __launch_bounds__(256, 2)
void conv_s2(const float* __restrict__ in0, const float* __restrict__ in1, int csplit,
             const float* __restrict__ wgt, const float* __restrict__ bias,
             float* __restrict__ out)
{
    __shared__ float s_in[2][65][68];   // in rows -1..63, cols -1..63 (65x65 used)
    __shared__ float s_w[2][16][12];

    const int tid  = threadIdx.x;
    const int tx   = tid & 7;           // out col group (4 cols)
    const int ty   = tid >> 3;          // 0..31 out row
    const int ocg  = blockIdx.y;        // 0..7
    const int b    = blockIdx.z;
    const int warp = tid >> 5;
    const int lane = tid & 31;

    float acc[16][4];
#pragma unroll
    for (int o = 0; o < 16; o++)
#pragma unroll
        for (int j = 0; j < 4; j++) acc[o][j] = 0.f;

    for (int ci0 = 0; ci0 < CI; ci0 += 2) {
        // weights: 2 ci x 16 oc x 9
#pragma unroll
        for (int idx = tid; idx < 2*16*9; idx += 256) {
            int ci = idx / 144; int r = idx - ci*144; int oc = r / 9; int kk = r - oc*9;
            s_w[ci][oc][(kk/3)*4 + (kk - (kk/3)*3)] =
                wgt[((size_t)(ocg*16 + oc) * CI + ci0 + ci) * 9 + kk];
        }
        // input tile: 2 ci x 65 x 65
#pragma unroll
        for (int ci = 0; ci < 2; ci++) {
            const int cg = ci0 + ci;
            const float* src = (cg < csplit)
                ? in0 + ((size_t)b * csplit + cg) * PP
                : in1 + ((size_t)b * (CI - csplit) + (cg - csplit)) * PP;
#pragma unroll
            for (int k = 0; k < 9; k++) {
                const int iy = warp + 8*k;
                if (k < 8 || iy < 65) {
                    const int gy = iy - 1;
                    const bool rowok = (unsigned)gy < HH;
                    const float* rowp = src + gy * WW;
                    float* srow = &s_in[ci][iy][0];
                    const int gx0 = lane - 1;
                    srow[lane]      = (rowok && (unsigned)gx0 < WW) ? rowp[gx0] : 0.f;
                    const int gx1 = lane + 31;
                    srow[lane + 32] = (rowok && gx1 < WW) ? rowp[gx1] : 0.f;
                    if (lane == 0) {
                        const int gx2 = 63;
                        srow[64] = rowok ? rowp[gx2] : 0.f;
                    }
                }
            }
        }
        __syncthreads();

#pragma unroll
        for (int ci = 0; ci < 2; ci++) {
#pragma unroll
            for (int k = 0; k < 3; k++) {
                const float4* rp = (const float4*)&s_in[ci][2*ty + k][8*tx];
                const float4 ra = rp[0], rb = rp[1], rc = rp[2];
                const float r[12] = {ra.x, ra.y, ra.z, ra.w,
                                     rb.x, rb.y, rb.z, rb.w,
                                     rc.x, rc.y, rc.z, rc.w};
#pragma unroll
                for (int oc = 0; oc < 16; oc++) {
                    const float4 w = *(const float4*)&s_w[ci][oc][k*4];
#pragma unroll
                    for (int j = 0; j < 4; j++) {
                        float a = acc[oc][j];
                        a = fmaf(r[2*j+0], w.x, a);
                        a = fmaf(r[2*j+1], w.y, a);
                        a = fmaf(r[2*j+2], w.z, a);
                        acc[oc][j] = a;
                    }
                }
            }
        }
        __syncthreads();
    }

#pragma unroll
    for (int oc = 0; oc < 16; oc++) {
        const float bv = bias[ocg*16 + oc];
        float4 v;
        v.x = lrelu(acc[oc][0] + bv);
        v.y = lrelu(acc[oc][1] + bv);
        v.z = lrelu(acc[oc][2] + bv);
        v.w = lrelu(acc[oc][3] + bv);
        size_t o = (((size_t)b * OCH + ocg*16 + oc) * OH + ty) * OW + tx*4;
        *(float4*)(out + o) = v;
    }
}

// ---------------------------------------------------------------------------
// RoIAlign(full image, 32x32 bins, sampling_ratio=2) of prev*attn -> slice 2.
// ---------------------------------------------------------------------------
__global__ void bo3_kernel(const float* __restrict__ prev,
                           const float* __restrict__ attn,
                           float* __restrict__ out /* slice-2 base */)
{
    const int idx = blockIdx.x * 256 + threadIdx.x;
    const int ox = idx & 31, oy = (idx >> 5) & 31, bc = idx >> 10;
    const int b = bc >> 7;
    const float* pv = prev + (size_t)bc * PP;
    const float* at = attn + (size_t)b * PP;
    const float BIN = 63.0f / 32.0f;

    float acc = 0.f;
#pragma unroll
    for (int sy = 0; sy < 2; sy++) {
        const float ys = ((float)oy + 0.25f + 0.5f * sy) * BIN;
        const int y0 = (int)ys;
        const int y1 = min(y0 + 1, HH - 1);
        const float ly = ys - (float)y0, hy = 1.f - ly;
#pragma unroll
        for (int sx = 0; sx < 2; sx++) {
            const float xs = ((float)ox + 0.25f + 0.5f * sx) * BIN;
            const int x0 = (int)xs;
            const int x1 = min(x0 + 1, WW - 1);
            const float lx = xs - (float)x0, hx = 1.f - lx;
            const float f00 = pv[y0*WW + x0] * at[y0*WW + x0];
            const float f01 = pv[y0*WW + x1] * at[y0*WW + x1];
            const float f10 = pv[y1*WW + x0] * at[y1*WW + x0];
            const float f11 = pv[y1*WW + x1] * at[y1*WW + x1];
            acc += hy * (hx * f00 + lx * f01) + ly * (hx * f10 + lx * f11);
        }
    }
    out[idx] = acc * 0.25f;
}

// ---------------------------------------------------------------------------
// slice0 = RoIAlign(l2) + aux + slice1 + slice2
// ---------------------------------------------------------------------------
__global__ void combine_kernel(const float* __restrict__ l2,
                               const float* __restrict__ aux,
                               float* __restrict__ out /* full d_out */)
{
    const int idx = blockIdx.x * 256 + threadIdx.x;
    const int ox = idx & 31, oy = (idx >> 5) & 31, bc = idx >> 10;
    const float* src = l2 + (size_t)bc * PP;
    const float BIN = 63.0f / 32.0f;

    float acc = 0.f;
#pragma unroll
    for (int sy = 0; sy < 2; sy++) {
        const float ys = ((float)oy + 0.25f + 0.5f * sy) * BIN;
        const int y0 = (int)ys;
        const int y1 = min(y0 + 1, HH - 1);
        const float ly = ys - (float)y0, hy = 1.f - ly;
#pragma unroll
        for (int sx = 0; sx < 2; sx++) {
            const float xs = ((float)ox + 0.25f + 0.5f * sx) * BIN;
            const int x0 = (int)xs;
            const int x1 = min(x0 + 1, WW - 1);
            const float lx = xs - (float)x0, hx = 1.f - lx;
            acc += hy * (hx * src[y0*WW + x0] + lx * src[y0*WW + x1])
                 + ly * (hx * src[y1*WW + x0] + lx * src[y1*WW + x1]);
        }
    }
    out[idx] = acc * 0.25f + aux[idx] + out[SLICE + idx] + out[2*SLICE + idx];
}

// ---------------------------------------------------------------------------
extern "C" void kernel_launch(void* const* d_in, const int* in_sizes, int n_in,
                              void* d_out, int out_size)
{
    const float* out1   = (const float*)d_in[0];
    const float* out2   = (const float*)d_in[1];
    const float* out3   = (const float*)d_in[2];
    const float* w1     = (const float*)d_in[3];
    const float* b1     = (const float*)d_in[4];
    const float* w2     = (const float*)d_in[5];
    const float* b2     = (const float*)d_in[6];
    const float* w3     = (const float*)d_in[7];
    const float* b3     = (const float*)d_in[8];
    const float* w_aux  = (const float*)d_in[9];
    const float* b_aux  = (const float*)d_in[10];
    const float* w_b2   = (const float*)d_in[11];
    const float* b_b2   = (const float*)d_in[12];
    const float* w_prev = (const float*)d_in[13];
    const float* b_prev = (const float*)d_in[14];
    const float* lin_w  = (const float*)d_in[15];
    const float* lin_b  = (const float*)d_in[16];
    float* out = (float*)d_out;

    float *l1, *l2, *l3, *prev, *aux, *attn;
    cudaGetSymbolAddress((void**)&l1,   g_l1);
    cudaGetSymbolAddress((void**)&l2,   g_l2);
    cudaGetSymbolAddress((void**)&l3,   g_l3);
    cudaGetSymbolAddress((void**)&prev, g_prev);
    cudaGetSymbolAddress((void**)&aux,  g_aux);
    cudaGetSymbolAddress((void**)&attn, g_attn);

    const dim3 gs1(2, OCH/8, BB);    // stride-1 convs: 2 y-tiles x 16 ocg x 32 b
    const dim3 gs2(1, OCH/16, BB);   // stride-2 convs: 8 ocg x 32 b
    const int  nPix = (int)(SLICE / 256);

    attn_kernel<<<BB, 256>>>(out1, lin_w, lin_b, attn);

    conv_s1<64 ><<<gs1, 256>>>(out1, nullptr, 64,  w1,     b1,     l1);
    conv_s1<128><<<gs1, 256>>>(l1,   nullptr, 128, w2,     b2,     l2);
    conv_s1<128><<<gs1, 256>>>(l2,   nullptr, 128, w3,     b3,     l3);
    conv_s1<128><<<gs1, 256>>>(out2, out3,    64,  w_prev, b_prev, prev);

    conv_s2<256><<<gs2, 256>>>(l1, l2,      128, w_b2,  b_b2,  out + SLICE);   // block_out2
    conv_s2<128><<<gs2, 256>>>(l3, nullptr, 128, w_aux, b_aux, aux);

    bo3_kernel<<<nPix, 256>>>(prev, attn, out + 2*SLICE);                      // block_out3
    combine_kernel<<<nPix, 256>>>(l2, aux, out);                               // block_out1 sum
}

// round 4
// speedup vs baseline: 1.6734x; 1.0585x over previous
#include <cuda_runtime.h>

// Problem constants
#define BB   32
#define CIN  64
#define OCH  128
#define HH   64
#define WW   64
#define PP   (HH*WW)          // 4096 pixels
#define OH   32
#define OW   32
#define SLICE ((size_t)BB*OCH*OH*OW)   // elements per output slice

typedef unsigned long long u64;

// Scratch (device globals: no allocation allowed in kernel_launch)
__device__ float g_l1  [BB*OCH*HH*WW];
__device__ float g_l2  [BB*OCH*HH*WW];
__device__ float g_l3  [BB*OCH*HH*WW];
__device__ float g_prev[BB*OCH*HH*WW];
__device__ float g_aux [BB*OCH*OH*OW];
__device__ float g_attn[BB*PP];

__device__ __forceinline__ float lrelu(float x) { return x >= 0.f ? x : 0.1f * x; }

// ---- packed f32x2 helpers (sm_103a) -----------------------------------
__device__ __forceinline__ u64 pk2(float lo, float hi) {
    u64 r; asm("mov.b64 %0,{%1,%2};" : "=l"(r) : "f"(lo), "f"(hi)); return r;
}
__device__ __forceinline__ u64 splat(float v) { return pk2(v, v); }
__device__ __forceinline__ void fma2(u64& d, u64 a, u64 b) {
    asm("fma.rn.f32x2 %0,%1,%2,%0;" : "+l"(d) : "l"(a), "l"(b));
}
__device__ __forceinline__ float2 unpk(u64 v) {
    float2 r; asm("mov.b64 {%0,%1},%2;" : "=f"(r.x), "=f"(r.y) : "l"(v)); return r;
}

// ---------------------------------------------------------------------------
// Attention: logits[b,p] = <lin_w[p,:], out1[b,:,p]> + lin_b[p]; softmax over p.
// ---------------------------------------------------------------------------
__global__ void attn_kernel(const float* __restrict__ out1,
                            const float* __restrict__ lin_w,
                            const float* __restrict__ lin_b,
                            float* __restrict__ attn)
{
    const int b   = blockIdx.x;
    const int tid = threadIdx.x;
    const float* xb = out1 + (size_t)b * CIN * PP;

    float logit[16];
    float lmax = -1e30f;
#pragma unroll
    for (int i = 0; i < 16; i++) {
        const int p = tid + i * 256;
        float acc = lin_b[p];
        const float4* wr = (const float4*)(lin_w + (size_t)p * CIN);
#pragma unroll
        for (int c4 = 0; c4 < CIN / 4; c4++) {
            float4 w4 = wr[c4];
            acc = fmaf(w4.x, xb[(c4*4+0)*PP + p], acc);
            acc = fmaf(w4.y, xb[(c4*4+1)*PP + p], acc);
            acc = fmaf(w4.z, xb[(c4*4+2)*PP + p], acc);
            acc = fmaf(w4.w, xb[(c4*4+3)*PP + p], acc);
        }
        logit[i] = acc;
        lmax = fmaxf(lmax, acc);
    }

    __shared__ float red[256];
    red[tid] = lmax; __syncthreads();
    for (int s = 128; s > 0; s >>= 1) {
        if (tid < s) red[tid] = fmaxf(red[tid], red[tid + s]);
        __syncthreads();
    }
    const float m = red[0]; __syncthreads();

    float lsum = 0.f;
#pragma unroll
    for (int i = 0; i < 16; i++) { logit[i] = expf(logit[i] - m); lsum += logit[i]; }
    red[tid] = lsum; __syncthreads();
    for (int s = 128; s > 0; s >>= 1) {
        if (tid < s) red[tid] += red[tid + s];
        __syncthreads();
    }
    const float inv = 1.0f / red[0];
#pragma unroll
    for (int i = 0; i < 16; i++)
        attn[(size_t)b * PP + tid + i * 256] = logit[i] * inv;
}

// ---------------------------------------------------------------------------
// Stride-1 3x3 conv + bias + lrelu, packed f32x2 over output-channel pairs.
// Block: tile 32 rows x 64 cols, 8 out-channels (4 oc-pairs), 256 threads.
// Thread: 1 row x 8 cols x 4 oc-pairs = 32 u64 accumulators (64 FMA lanes).
// Weights pre-interleaved in smem as (w[2o],w[2o+1]) u64 pairs.
// ---------------------------------------------------------------------------
template<int CI>
__global__ __launch_bounds__(256, 2)
void conv_s1(const float* __restrict__ in0, const float* __restrict__ in1, int csplit,
             const float* __restrict__ wgt, const float* __restrict__ bias,
             float* __restrict__ out)
{
    __shared__ float s_in[4][34][68];   // 34 halo rows x 66 used cols
    __shared__ u64   s_w[4][4][12];     // [ci][oc2][k*4 + t] packed (lo,hi) oc pair

    const int tid  = threadIdx.x;
    const int tx   = tid & 7;           // col group
    const int ty   = tid >> 3;          // 0..31 row in tile
    const int x8   = tx * 8;
    const int ty0  = blockIdx.x * 32;
    const int ocg  = blockIdx.y;        // 0..15
    const int b    = blockIdx.z;
    const int warp = tid >> 5;
    const int lane = tid & 31;

    u64 acc2[4][8];
#pragma unroll
    for (int o = 0; o < 4; o++)
#pragma unroll
        for (int j = 0; j < 8; j++) acc2[o][j] = 0ULL;

    for (int ci0 = 0; ci0 < CI; ci0 += 4) {
        // ---- weights: 4 ci x 8 oc x 9, interleaved into oc-pair u64 slots ----
#pragma unroll
        for (int idx = tid; idx < 4*8*9; idx += 256) {
            int ci = idx / 72; int r = idx - ci*72; int oc = r / 9; int kk = r - oc*9;
            int k = kk / 3, t = kk - k*3;
            ((float*)&s_w[ci][oc >> 1][k*4 + t])[oc & 1] =
                wgt[((size_t)(ocg*8 + oc) * CI + ci0 + ci) * 9 + kk];
        }
        // ---- input tile: 4 ci x 34 rows x 66 cols, no div/mod ----
#pragma unroll
        for (int ci = 0; ci < 4; ci++) {
            const int cg = ci0 + ci;
            const float* src = (cg < csplit)
                ? in0 + ((size_t)b * csplit + cg) * PP
                : in1 + ((size_t)b * (CI - csplit) + (cg - csplit)) * PP;
#pragma unroll
            for (int k = 0; k < 5; k++) {
                const int iy = warp + 8*k;
                if (k < 4 || iy < 34) {
                    const int gy = ty0 - 1 + iy;
                    const bool rowok = (unsigned)gy < HH;
                    const float* rowp = src + gy * WW;
                    float* srow = &s_in[ci][iy][0];
                    const int gx0 = lane - 1;
                    srow[lane]      = (rowok && (unsigned)gx0 < WW) ? rowp[gx0] : 0.f;
                    const int gx1 = lane + 31;
                    srow[lane + 32] = (rowok && gx1 < WW) ? rowp[gx1] : 0.f;
                    if (lane < 2) {
                        const int gx2 = lane + 63;
                        srow[lane + 64] = (rowok && gx2 < WW) ? rowp[gx2] : 0.f;
                    }
                }
            }
        }
        __syncthreads();

        // ---- compute: FFMA2 everywhere ----
#pragma unroll
        for (int ci = 0; ci < 4; ci++) {
#pragma unroll
            for (int k = 0; k < 3; k++) {
                const float4* rp = (const float4*)&s_in[ci][ty + k][x8];
                const float4 ra = rp[0], rb = rp[1], rc = rp[2];
                u64 rs[10];
                rs[0] = splat(ra.x); rs[1] = splat(ra.y); rs[2] = splat(ra.z); rs[3] = splat(ra.w);
                rs[4] = splat(rb.x); rs[5] = splat(rb.y); rs[6] = splat(rb.z); rs[7] = splat(rb.w);
                rs[8] = splat(rc.x); rs[9] = splat(rc.y);
#pragma unroll
                for (int o2 = 0; o2 < 4; o2++) {
                    const ulonglong2 w01 = *(const ulonglong2*)&s_w[ci][o2][k*4];
                    const u64 w2 = s_w[ci][o2][k*4 + 2];
#pragma unroll
                    for (int j = 0; j < 8; j++) {
                        fma2(acc2[o2][j], rs[j],     w01.x);
                        fma2(acc2[o2][j], rs[j + 1], w01.y);
                        fma2(acc2[o2][j], rs[j + 2], w2);
                    }
                }
            }
        }
        __syncthreads();
    }

#pragma unroll
    for (int o2 = 0; o2 < 4; o2++) {
        const float b0 = bias[ocg*8 + 2*o2];
        const float b1 = bias[ocg*8 + 2*o2 + 1];
        float r0[8], r1[8];
#pragma unroll
        for (int j = 0; j < 8; j++) {
            float2 v = unpk(acc2[o2][j]);
            r0[j] = lrelu(v.x + b0);
            r1[j] = lrelu(v.y + b1);
        }
        size_t o0 = (((size_t)b * OCH + ocg*8 + 2*o2)     * HH + ty0 + ty) * WW + x8;
        size_t o1 = (((size_t)b * OCH + ocg*8 + 2*o2 + 1) * HH + ty0 + ty) * WW + x8;
        *(float4*)(out + o0)     = make_float4(r0[0], r0[1], r0[2], r0[3]);
        *(float4*)(out + o0 + 4) = make_float4(r0[4], r0[5], r0[6], r0[7]);
        *(float4*)(out + o1)     = make_float4(r1[0], r1[1], r1[2], r1[3]);
        *(float4*)(out + o1 + 4) = make_float4(r1[4], r1[5], r1[6], r1[7]);
    }
}

// ---------------------------------------------------------------------------
// Stride-2 3x3 conv + bias + lrelu (pad 1). Output 32x32 (full image / block).
// Packed f32x2 over oc pairs: 16 oc -> 8 pairs; thread: 1 row x 4 cols.
// ---------------------------------------------------------------------------
template<int CI>
__global__ __launch_bounds__(256, 2)
void conv_s2(const float* __restrict__ in0, const float* __restrict__ in1, int csplit,
             const float* __restrict__ wgt, const float* __restrict__ bias,
             float* __restrict__ out)
{
    __shared__ float s_in[2][65][68];   // in rows -1..63, cols -1..63 (65x65 used)
    __shared__ u64   s_w[2][8][12];     // [ci][oc2][k*4+t] packed oc pair

    const int tid  = threadIdx.x;
    const int tx   = tid & 7;           // out col group (4 cols)
    const int ty   = tid >> 3;          // 0..31 out row
    const int ocg  = blockIdx.y;        // 0..7
    const int b    = blockIdx.z;
    const int warp = tid >> 5;
    const int lane = tid & 31;

    u64 acc2[8][4];
#pragma unroll
    for (int o = 0; o < 8; o++)
#pragma unroll
        for (int j = 0; j < 4; j++) acc2[o][j] = 0ULL;

    for (int ci0 = 0; ci0 < CI; ci0 += 2) {
        // weights: 2 ci x 16 oc x 9 -> oc-pair u64 slots
#pragma unroll
        for (int idx = tid; idx < 2*16*9; idx += 256) {
            int ci = idx / 144; int r = idx - ci*144; int oc = r / 9; int kk = r - oc*9;
            int k = kk / 3, t = kk - k*3;
            ((float*)&s_w[ci][oc >> 1][k*4 + t])[oc & 1] =
                wgt[((size_t)(ocg*16 + oc) * CI + ci0 + ci) * 9 + kk];
        }
        // input tile: 2 ci x 65 x 65
#pragma unroll
        for (int ci = 0; ci < 2; ci++) {
            const int cg = ci0 + ci;
            const float* src = (cg < csplit)
                ? in0 + ((size_t)b * csplit + cg) * PP
                : in1 + ((size_t)b * (CI - csplit) + (cg - csplit)) * PP;
#pragma unroll
            for (int k = 0; k < 9; k++) {
                const int iy = warp + 8*k;
                if (k < 8 || iy < 65) {
                    const int gy = iy - 1;
                    const bool rowok = (unsigned)gy < HH;
                    const float* rowp = src + gy * WW;
                    float* srow = &s_in[ci][iy][0];
                    const int gx0 = lane - 1;
                    srow[lane]      = (rowok && (unsigned)gx0 < WW) ? rowp[gx0] : 0.f;
                    const int gx1 = lane + 31;
                    srow[lane + 32] = (rowok && gx1 < WW) ? rowp[gx1] : 0.f;
                    if (lane == 0) {
                        srow[64] = rowok ? rowp[63] : 0.f;
                    }
                }
            }
        }
        __syncthreads();

#pragma unroll
        for (int ci = 0; ci < 2; ci++) {
#pragma unroll
            for (int k = 0; k < 3; k++) {
                const float4* rp = (const float4*)&s_in[ci][2*ty + k][8*tx];
                const float4 ra = rp[0], rb = rp[1], rc = rp[2];
                u64 rs[10];
                rs[0] = splat(ra.x); rs[1] = splat(ra.y); rs[2] = splat(ra.z); rs[3] = splat(ra.w);
                rs[4] = splat(rb.x); rs[5] = splat(rb.y); rs[6] = splat(rb.z); rs[7] = splat(rb.w);
                rs[8] = splat(rc.x); rs[9] = splat(rc.y);
#pragma unroll
                for (int o2 = 0; o2 < 8; o2++) {
                    const ulonglong2 w01 = *(const ulonglong2*)&s_w[ci][o2][k*4];
                    const u64 w2 = s_w[ci][o2][k*4 + 2];
#pragma unroll
                    for (int j = 0; j < 4; j++) {
                        fma2(acc2[o2][j], rs[2*j],     w01.x);
                        fma2(acc2[o2][j], rs[2*j + 1], w01.y);
                        fma2(acc2[o2][j], rs[2*j + 2], w2);
                    }
                }
            }
        }
        __syncthreads();
    }

#pragma unroll
    for (int o2 = 0; o2 < 8; o2++) {
        const float b0 = bias[ocg*16 + 2*o2];
        const float b1 = bias[ocg*16 + 2*o2 + 1];
        float r0[4], r1[4];
#pragma unroll
        for (int j = 0; j < 4; j++) {
            float2 v = unpk(acc2[o2][j]);
            r0[j] = lrelu(v.x + b0);
            r1[j] = lrelu(v.y + b1);
        }
        size_t oo0 = (((size_t)b * OCH + ocg*16 + 2*o2)     * OH + ty) * OW + tx*4;
        size_t oo1 = (((size_t)b * OCH + ocg*16 + 2*o2 + 1) * OH + ty) * OW + tx*4;
        *(float4*)(out + oo0) = make_float4(r0[0], r0[1], r0[2], r0[3]);
        *(float4*)(out + oo1) = make_float4(r1[0], r1[1], r1[2], r1[3]);
    }
}

// ---------------------------------------------------------------------------
// RoIAlign(full image, 32x32 bins, sampling_ratio=2) of prev*attn -> slice 2.
// ---------------------------------------------------------------------------
__global__ void bo3_kernel(const float* __restrict__ prev,
                           const float* __restrict__ attn,
                           float* __restrict__ out /* slice-2 base */)
{
    const int idx = blockIdx.x * 256 + threadIdx.x;
    const int ox = idx & 31, oy = (idx >> 5) & 31, bc = idx >> 10;
    const int b = bc >> 7;
    const float* pv = prev + (size_t)bc * PP;
    const float* at = attn + (size_t)b * PP;
    const float BIN = 63.0f / 32.0f;

    float acc = 0.f;
#pragma unroll
    for (int sy = 0; sy < 2; sy++) {
        const float ys = ((float)oy + 0.25f + 0.5f * sy) * BIN;
        const int y0 = (int)ys;
        const int y1 = min(y0 + 1, HH - 1);
        const float ly = ys - (float)y0, hy = 1.f - ly;
#pragma unroll
        for (int sx = 0; sx < 2; sx++) {
            const float xs = ((float)ox + 0.25f + 0.5f * sx) * BIN;
            const int x0 = (int)xs;
            const int x1 = min(x0 + 1, WW - 1);
            const float lx = xs - (float)x0, hx = 1.f - lx;
            const float f00 = pv[y0*WW + x0] * at[y0*WW + x0];
            const float f01 = pv[y0*WW + x1] * at[y0*WW + x1];
            const float f10 = pv[y1*WW + x0] * at[y1*WW + x0];
            const float f11 = pv[y1*WW + x1] * at[y1*WW + x1];
            acc += hy * (hx * f00 + lx * f01) + ly * (hx * f10 + lx * f11);
        }
    }
    out[idx] = acc * 0.25f;
}

// ---------------------------------------------------------------------------
// slice0 = RoIAlign(l2) + aux + slice1 + slice2
// ---------------------------------------------------------------------------
__global__ void combine_kernel(const float* __restrict__ l2,
                               const float* __restrict__ aux,
                               float* __restrict__ out /* full d_out */)
{
    const int idx = blockIdx.x * 256 + threadIdx.x;
    const int ox = idx & 31, oy = (idx >> 5) & 31, bc = idx >> 10;
    const float* src = l2 + (size_t)bc * PP;
    const float BIN = 63.0f / 32.0f;

    float acc = 0.f;
#pragma unroll
    for (int sy = 0; sy < 2; sy++) {
        const float ys = ((float)oy + 0.25f + 0.5f * sy) * BIN;
        const int y0 = (int)ys;
        const int y1 = min(y0 + 1, HH - 1);
        const float ly = ys - (float)y0, hy = 1.f - ly;
#pragma unroll
        for (int sx = 0; sx < 2; sx++) {
            const float xs = ((float)ox + 0.25f + 0.5f * sx) * BIN;
            const int x0 = (int)xs;
            const int x1 = min(x0 + 1, WW - 1);
            const float lx = xs - (float)x0, hx = 1.f - lx;
            acc += hy * (hx * src[y0*WW + x0] + lx * src[y0*WW + x1])
                 + ly * (hx * src[y1*WW + x0] + lx * src[y1*WW + x1]);
        }
    }
    out[idx] = acc * 0.25f + aux[idx] + out[SLICE + idx] + out[2*SLICE + idx];
}

// ---------------------------------------------------------------------------
extern "C" void kernel_launch(void* const* d_in, const int* in_sizes, int n_in,
                              void* d_out, int out_size)
{
    const float* out1   = (const float*)d_in[0];
    const float* out2   = (const float*)d_in[1];
    const float* out3   = (const float*)d_in[2];
    const float* w1     = (const float*)d_in[3];
    const float* b1     = (const float*)d_in[4];
    const float* w2     = (const float*)d_in[5];
    const float* b2     = (const float*)d_in[6];
    const float* w3     = (const float*)d_in[7];
    const float* b3     = (const float*)d_in[8];
    const float* w_aux  = (const float*)d_in[9];
    const float* b_aux  = (const float*)d_in[10];
    const float* w_b2   = (const float*)d_in[11];
    const float* b_b2   = (const float*)d_in[12];
    const float* w_prev = (const float*)d_in[13];
    const float* b_prev = (const float*)d_in[14];
    const float* lin_w  = (const float*)d_in[15];
    const float* lin_b  = (const float*)d_in[16];
    float* out = (float*)d_out;

    float *l1, *l2, *l3, *prev, *aux, *attn;
    cudaGetSymbolAddress((void**)&l1,   g_l1);
    cudaGetSymbolAddress((void**)&l2,   g_l2);
    cudaGetSymbolAddress((void**)&l3,   g_l3);
    cudaGetSymbolAddress((void**)&prev, g_prev);
    cudaGetSymbolAddress((void**)&aux,  g_aux);
    cudaGetSymbolAddress((void**)&attn, g_attn);

    const dim3 gs1(2, OCH/8, BB);    // stride-1 convs: 2 y-tiles x 16 ocg x 32 b
    const dim3 gs2(1, OCH/16, BB);   // stride-2 convs: 8 ocg x 32 b
    const int  nPix = (int)(SLICE / 256);

    attn_kernel<<<BB, 256>>>(out1, lin_w, lin_b, attn);

    conv_s1<64 ><<<gs1, 256>>>(out1, nullptr, 64,  w1,     b1,     l1);
    conv_s1<128><<<gs1, 256>>>(l1,   nullptr, 128, w2,     b2,     l2);
    conv_s1<128><<<gs1, 256>>>(l2,   nullptr, 128, w3,     b3,     l3);
    conv_s1<128><<<gs1, 256>>>(out2, out3,    64,  w_prev, b_prev, prev);

    conv_s2<256><<<gs2, 256>>>(l1, l2,      128, w_b2,  b_b2,  out + SLICE);   // block_out2
    conv_s2<128><<<gs2, 256>>>(l3, nullptr, 128, w_aux, b_aux, aux);

    bo3_kernel<<<nPix, 256>>>(prev, attn, out + 2*SLICE);                      // block_out3
    combine_kernel<<<nPix, 256>>>(l2, aux, out);                               // block_out1 sum
}